// round 2
// baseline (speedup 1.0000x reference)
#include <cuda_runtime.h>
#include <cstdint>

#define NTHREADS 256
#define BT 32
#define STR 36

// shared-memory float offsets
#define OFF_WSM 0        // staged weights, max 82*128 = 10496 floats
#define OFF_WV  10496    // Wv_all rearranged [128][128] = 16384
#define OFF_AT  26880    // transposed activations, max K=82 -> 82*36 = 2952
#define OFF_X1  29832    // x1 then x3_self, 64*36 = 2304
#define OFF_SEL 32136    // sel then enc then x2_others, 128*36 = 4608
#define OFF_T   36744    // t[h][f][b], 4*128*36 = 18432
#define OFF_M   55176
#define OFF_S   55304
#define OFF_AL  55432
#define OFF_P   55560
#define SMEM_FLOATS 55688   // 222752 bytes

__device__ __forceinline__ void ldw(float* dst, const float* __restrict__ src, int n){
    for (int i = threadIdx.x*4; i < n; i += NTHREADS*4)
        *reinterpret_cast<float4*>(dst+i) = *reinterpret_cast<const float4*>(src+i);
}

__device__ __forceinline__ void ld_inT(float* dst, const float* __restrict__ A, int KA,
                                       const float* __restrict__ Bp, int KB, int b0){
    int K = KA + KB;
    for (int idx = threadIdx.x; idx < K*BT; idx += NTHREADS){
        int bl = idx / K, k = idx - bl*K;
        float v = (k < KA) ? A[(size_t)(b0+bl)*KA + k]
                           : Bp[(size_t)(b0+bl)*KB + (k-KA)];
        dst[k*STR + bl] = v;
    }
}

// OUT[col][row] = act( IN[.][row] @ Wsm[.][col] + bias ), per-thread 4 rows x NC cols
template<int K, int N, bool RELU, bool BIAS>
__device__ __forceinline__ void gemm_stage(const float* __restrict__ Wsm,
                                           const float* __restrict__ inT,
                                           float* __restrict__ outT,
                                           const float* __restrict__ biasG,
                                           int w, int cj){
    constexpr int NC = N/32;
    float acc[4][NC];
#pragma unroll
    for (int r=0;r<4;r++)
#pragma unroll
        for (int c=0;c<NC;c++) acc[r][c]=0.f;
    const float* ap = inT + w*4;
    const float* wp = Wsm + cj*NC;
#pragma unroll 4
    for (int k=0;k<K;k++){
        float4 a4 = *reinterpret_cast<const float4*>(ap + k*STR);
        float av[4] = {a4.x,a4.y,a4.z,a4.w};
        float wv[NC];
        if constexpr (NC==4){
            float4 w4 = *reinterpret_cast<const float4*>(wp + k*N);
            wv[0]=w4.x; wv[1]=w4.y; wv[2]=w4.z; wv[3]=w4.w;
        } else {
            float2 w2 = *reinterpret_cast<const float2*>(wp + k*N);
            wv[0]=w2.x; wv[1]=w2.y;
        }
#pragma unroll
        for (int c=0;c<NC;c++)
#pragma unroll
            for (int r=0;r<4;r++)
                acc[r][c] = fmaf(av[r], wv[c], acc[r][c]);
    }
#pragma unroll
    for (int c=0;c<NC;c++){
        int col = cj*NC + c;
        float bb = BIAS ? biasG[col] : 0.f;
#pragma unroll
        for (int r=0;r<4;r++){
            float v = acc[r][c] + bb;
            if (RELU) v = fmaxf(v, 0.f);
            outT[col*STR + w*4 + r] = v;
        }
    }
}

__global__ void __launch_bounds__(NTHREADS,1) ac_kernel(
    const float* __restrict__ state_one, const float* __restrict__ act_one,
    const float* __restrict__ state_others, const float* __restrict__ act_others,
    const float* __restrict__ W1, const float* __restrict__ b1,
    const float* __restrict__ W2, const float* __restrict__ b2,
    const float* __restrict__ w3_self,
    const float* __restrict__ We, const float* __restrict__ be,
    const float* __restrict__ Wk, const float* __restrict__ Wq,
    const float* __restrict__ Wv, const float* __restrict__ bv,
    const float* __restrict__ w3_others,
    const float* __restrict__ Wout, const float* __restrict__ bout,
    float* __restrict__ out, int B)
{
    extern __shared__ float sm[];
    float* WSM  = sm + OFF_WSM;
    float* WV   = sm + OFF_WV;
    float* aT   = sm + OFF_AT;
    float* x1T  = sm + OFF_X1;
    float* selT = sm + OFF_SEL;
    float* tT   = sm + OFF_T;
    float* sm_m = sm + OFF_M;
    float* sm_s = sm + OFF_S;
    float* sm_al= sm + OFF_AL;
    float* sm_p = sm + OFF_P;

    const int tid = threadIdx.x;
    const int w = tid >> 5, cj = tid & 31;
    const int b0 = blockIdx.x * BT;

    // stage inputs + W1; also load Wv_all (persistent, rearranged [f][h*32+d])
    ldw(WSM, W1, 78*64);
    ld_inT(aT, state_one, 64, act_one, 14, b0);
    for (int idx = tid; idx < 128*128; idx += NTHREADS){
        int n = idx & 127, f = idx >> 7;
        int h = n >> 5, d = n & 31;
        WV[idx] = Wv[h*4096 + f*32 + d];
    }
    __syncthreads();

    // S1: x1 = relu(x @ W1 + b1)
    gemm_stage<78,64,true,true>(WSM, aT, x1T, b1, w, cj);
    __syncthreads();

    // S4: sel = x1 @ Wq_all  (Wsm[k][h*32+d] = Wq[h][k][d])
    for (int idx = tid; idx < 64*128; idx += NTHREADS){
        int n = idx & 127, k = idx >> 7;
        int h = n >> 5, d = n & 31;
        WSM[idx] = Wq[h*2048 + k*32 + d];
    }
    __syncthreads();
    gemm_stage<64,128,false,false>(WSM, x1T, selT, nullptr, w, cj);
    __syncthreads();

    // S5: t[h,b,f] = sum_d Wk[h,f,d] * sel[h,b,d]   (Wsm[d][f] = Wk[h][f][d])
    for (int h = 0; h < 4; h++){
        for (int idx = tid; idx < 32*128; idx += NTHREADS){
            int f = idx & 127, d = idx >> 7;
            WSM[idx] = Wk[h*4096 + f*32 + d];
        }
        __syncthreads();
        gemm_stage<32,128,false,false>(WSM, selT + h*32*STR, tT + h*128*STR, nullptr, w, cj);
        __syncthreads();
    }

    // S2: x2 = relu(x1 @ W2 + b2) -> aT
    ldw(WSM, W2, 64*64);
    __syncthreads();
    gemm_stage<64,64,true,true>(WSM, x1T, aT, b2, w, cj);
    __syncthreads();

    // S3: x3_self = x2 @ w3_self -> x1T (x1 dead)
    ldw(WSM, w3_self, 64*64);
    __syncthreads();
    gemm_stage<64,64,false,false>(WSM, aT, x1T, nullptr, w, cj);

    // init online softmax
    if (tid < 128){ sm_m[tid] = -1e30f; sm_s[tid] = 0.f; }
    float ov[4][4];
#pragma unroll
    for (int r=0;r<4;r++)
#pragma unroll
        for (int c=0;c<4;c++) ov[r][c] = 0.f;

    // agent loop
    for (int a = 0; a < 7; a++){
        __syncthreads();
        ld_inT(aT, state_others + (size_t)a*B*64, 64,
                   act_others  + (size_t)a*B*18, 18, b0);
        ldw(WSM, We + (size_t)a*82*128, 82*128);
        __syncthreads();
        // enc = relu(inp @ We[a] + be[a]) -> selT
        gemm_stage<82,128,true,true>(WSM, aT, selT, be + a*128, w, cj);
        __syncthreads();
        // logits + online-softmax stats (threads 0..127: h = tid/32, b = lane)
        if (tid < 128){
            int bl = tid & 31, h = tid >> 5;
            const float* ep = selT + bl;
            const float* tp = tT + h*128*STR + bl;
            float acc = 0.f;
#pragma unroll 8
            for (int f = 0; f < 128; f++)
                acc = fmaf(ep[f*STR], tp[f*STR], acc);
            float lg = acc * 0.17677669529663687f;   // 1/sqrt(32)
            float mo = sm_m[tid];
            float mn = fmaxf(mo, lg);
            float al = __expf(mo - mn);
            float pp = __expf(lg - mn);
            sm_s[tid] = sm_s[tid]*al + pp;
            sm_m[tid] = mn;
            sm_al[tid] = al;
            sm_p[tid] = pp;
        }
        __syncthreads();
        // vals = relu(enc @ Wv_all + bv); ov = ov*alpha + p*vals  (regs)
        {
            float acc[4][4];
#pragma unroll
            for (int r=0;r<4;r++)
#pragma unroll
                for (int c=0;c<4;c++) acc[r][c]=0.f;
            const float* ap = selT + w*4;
            const float* wp = WV + cj*4;
#pragma unroll 4
            for (int k = 0; k < 128; k++){
                float4 a4 = *reinterpret_cast<const float4*>(ap + k*STR);
                float4 w4 = *reinterpret_cast<const float4*>(wp + k*128);
                float av[4] = {a4.x,a4.y,a4.z,a4.w};
                float wv[4] = {w4.x,w4.y,w4.z,w4.w};
#pragma unroll
                for (int c=0;c<4;c++)
#pragma unroll
                    for (int r=0;r<4;r++)
                        acc[r][c] = fmaf(av[r], wv[c], acc[r][c]);
            }
#pragma unroll
            for (int c=0;c<4;c++){
                int col = cj*4 + c, h = col >> 5;
                float bvv = bv[col];
#pragma unroll
                for (int r=0;r<4;r++){
                    int bl = w*4 + r;
                    float v = fmaxf(acc[r][c] + bvv, 0.f);
                    float al = sm_al[h*32 + bl];
                    float pp = sm_p[h*32 + bl];
                    ov[r][c] = ov[r][c]*al + pp*v;
                }
            }
        }
    }
    __syncthreads();

    // S7: x2_others = ov / s  -> selT (enc dead)
#pragma unroll
    for (int c=0;c<4;c++){
        int col = cj*4 + c, h = col >> 5;
#pragma unroll
        for (int r=0;r<4;r++){
            int bl = w*4 + r;
            selT[col*STR + bl] = ov[r][c] / sm_s[h*32 + bl];
        }
    }
    ldw(WSM, w3_others, 128*64);
    __syncthreads();

    // S8: x3o = x2o @ w3_others; x3 = relu(x3_self + x3o); out = x3 @ Wout + bout
    {
        float acc[4][2];
#pragma unroll
        for (int r=0;r<4;r++){ acc[r][0]=0.f; acc[r][1]=0.f; }
        const float* ap = selT + w*4;
        const float* wp = WSM + cj*2;
#pragma unroll 4
        for (int k = 0; k < 128; k++){
            float4 a4 = *reinterpret_cast<const float4*>(ap + k*STR);
            float2 w2 = *reinterpret_cast<const float2*>(wp + k*64);
            float av[4] = {a4.x,a4.y,a4.z,a4.w};
#pragma unroll
            for (int r=0;r<4;r++){
                acc[r][0] = fmaf(av[r], w2.x, acc[r][0]);
                acc[r][1] = fmaf(av[r], w2.y, acc[r][1]);
            }
        }
        float pr[4] = {0.f,0.f,0.f,0.f};
#pragma unroll
        for (int c=0;c<2;c++){
            int col = cj*2 + c;
            float wo = Wout[col];
#pragma unroll
            for (int r=0;r<4;r++){
                float x3 = fmaxf(acc[r][c] + x1T[col*STR + w*4 + r], 0.f);
                pr[r] = fmaf(x3, wo, pr[r]);
            }
        }
#pragma unroll
        for (int o = 16; o > 0; o >>= 1){
#pragma unroll
            for (int r=0;r<4;r++)
                pr[r] += __shfl_xor_sync(0xffffffffu, pr[r], o);
        }
        if (cj == 0){
            float bo = bout[0];
#pragma unroll
            for (int r=0;r<4;r++)
                out[b0 + w*4 + r] = pr[r] + bo;
        }
    }
}

extern "C" void kernel_launch(void* const* d_in, const int* in_sizes, int n_in,
                              void* d_out, int out_size)
{
    const float* state_one    = (const float*)d_in[0];
    const float* act_one      = (const float*)d_in[1];
    const float* state_others = (const float*)d_in[2];
    const float* act_others   = (const float*)d_in[3];
    const float* W1   = (const float*)d_in[4];
    const float* b1   = (const float*)d_in[5];
    const float* W2   = (const float*)d_in[6];
    const float* b2   = (const float*)d_in[7];
    const float* w3s  = (const float*)d_in[8];
    const float* We   = (const float*)d_in[9];
    const float* be   = (const float*)d_in[10];
    const float* Wk   = (const float*)d_in[11];
    const float* Wq   = (const float*)d_in[12];
    const float* Wv   = (const float*)d_in[13];
    const float* bv   = (const float*)d_in[14];
    const float* w3o  = (const float*)d_in[15];
    const float* Wout = (const float*)d_in[16];
    const float* bout = (const float*)d_in[17];
    float* out = (float*)d_out;

    int B = in_sizes[0] / 64;
    int smem_bytes = SMEM_FLOATS * sizeof(float);
    cudaFuncSetAttribute(ac_kernel, cudaFuncAttributeMaxDynamicSharedMemorySize, smem_bytes);
    dim3 grid(B / BT), block(NTHREADS);
    ac_kernel<<<grid, block, smem_bytes>>>(
        state_one, act_one, state_others, act_others,
        W1, b1, W2, b2, w3s, We, be, Wk, Wq, Wv, bv, w3o, Wout, bout, out, B);
}

// round 3
// speedup vs baseline: 1.3220x; 1.3220x over previous
#include <cuda_runtime.h>
#include <cstdint>

#define NTHREADS 256
#define BT 64
#define LSCALE 0.17677669529663687f  // 1/sqrt(32)

// ---------------- smem layout (floats) ----------------
#define OFF_WVPK  0        // Wv packed, 16*4*2*32*4 = 16384
#define OFF_WSPK  16384    // staging buffer (We/Wk/W1/W2/Wq/w3s/w3o), 16384
#define OFF_IN    32768    // [64][132] inputs / keys / x2_others = 8448
#define OFF_ACT2  41216    // [64][132] sel-temp / x2 / enc = 8448
#define OFF_X1    49664    // [64][68]  x1 then x3_self = 4352
#define OFF_BIAS  54016    // b1(64) b2(64) bv(128) be(7*128) Wout(64) = 1216
#define OFF_AL    55232    // [4][64] alpha (then s)
#define OFF_P     55488    // [4][64] p
#define OFF_RED   55744    // [4][64] final reduction
#define SMEM_FLOATS 56000  // 224000 bytes

__device__ __forceinline__ float tf32f(float x){
    uint32_t u; asm("cvt.rna.tf32.f32 %0, %1;" : "=r"(u) : "f"(x));
    return __uint_as_float(u);
}

__device__ __forceinline__ void mma8(float* c, const uint32_t* a, uint32_t b0, uint32_t b1){
    asm volatile("mma.sync.aligned.m16n8k8.row.col.f32.tf32.tf32.f32 "
        "{%0,%1,%2,%3},{%4,%5,%6,%7},{%8,%9},{%0,%1,%2,%3};"
        : "+f"(c[0]),"+f"(c[1]),"+f"(c[2]),"+f"(c[3])
        : "r"(a[0]),"r"(a[1]),"r"(a[2]),"r"(a[3]),"r"(b0),"r"(b1));
}

// Stage weights into fragment-major packed layout.
// dst[i], i = (((ks*4+nw)*2+half)*32+lane)*NTW + tile
// k = ks*8 + lane%4 + half*4 ; n = nw*8*NTW + tile*8 + lane/4
#define STAGE_PK(DST, KACT, KS, NTW, SRCEXPR) do {                         \
    for (int i_ = threadIdx.x; i_ < (KS)*(NTW)*256; i_ += NTHREADS){       \
        int tile = i_ % (NTW); int rest_ = i_ / (NTW);                     \
        int lane_ = rest_ & 31; rest_ >>= 5;                               \
        int half_ = rest_ & 1;  rest_ >>= 1;                               \
        int nw_ = rest_ & 3;    int ks_ = rest_ >> 2;                      \
        int k = ks_*8 + (lane_&3) + half_*4;                               \
        int n = nw_*(8*(NTW)) + tile*8 + (lane_>>2);                       \
        float v_ = 0.f;                                                    \
        if (k < (KACT)) { v_ = (SRCEXPR); }                                \
        (DST)[i_] = tf32f(v_);                                             \
    } } while(0)

// GEMM: C[2][NTW][4] = A(BT x K, stride astr) @ Bpk ; warp tile m32 x (8*NTW)
template<int KS, int NTW>
__device__ __forceinline__ void run_mma(const float* __restrict__ A, int astr,
                                        const float* __restrict__ Bpk,
                                        float (&C)[2][NTW][4],
                                        int warp_m, int warp_n, int g, int t, int lane)
{
#pragma unroll
    for (int mt=0;mt<2;mt++)
#pragma unroll
        for (int nt=0;nt<NTW;nt++)
#pragma unroll
            for (int j=0;j<4;j++) C[mt][nt][j]=0.f;

    const float* a0p = A + (warp_m*32 + g)*astr + t;
#pragma unroll
    for (int ks=0; ks<KS; ks++){
        uint32_t a[2][4];
#pragma unroll
        for (int mt=0;mt<2;mt++){
            const float* ap = a0p + mt*16*astr + ks*8;
            a[mt][0] = __float_as_uint(ap[0]);
            a[mt][1] = __float_as_uint(ap[8*astr]);
            a[mt][2] = __float_as_uint(ap[4]);
            a[mt][3] = __float_as_uint(ap[8*astr + 4]);
        }
        const float* bp = Bpk + ((size_t)((ks*4 + warp_n)*2)*32 + lane)*NTW;
        uint32_t b0[NTW], b1[NTW];
        if constexpr (NTW==4){
            float4 x = *reinterpret_cast<const float4*>(bp);
            float4 y = *reinterpret_cast<const float4*>(bp + 32*4);
            b0[0]=__float_as_uint(x.x); b0[1]=__float_as_uint(x.y);
            b0[2]=__float_as_uint(x.z); b0[3]=__float_as_uint(x.w);
            b1[0]=__float_as_uint(y.x); b1[1]=__float_as_uint(y.y);
            b1[2]=__float_as_uint(y.z); b1[3]=__float_as_uint(y.w);
        } else {
            float2 x = *reinterpret_cast<const float2*>(bp);
            float2 y = *reinterpret_cast<const float2*>(bp + 32*2);
            b0[0]=__float_as_uint(x.x); b0[1]=__float_as_uint(x.y);
            b1[0]=__float_as_uint(y.x); b1[1]=__float_as_uint(y.y);
        }
#pragma unroll
        for (int mt=0;mt<2;mt++)
#pragma unroll
            for (int nt=0;nt<NTW;nt++)
                mma8(C[mt][nt], a[mt], b0[nt], b1[nt]);
    }
}

template<int NTW, bool RELU, bool BIAS, bool CVT>
__device__ __forceinline__ void epi_store(float (&C)[2][NTW][4], float* __restrict__ O, int ostr,
                                          const float* __restrict__ bias,
                                          int warp_m, int warp_n, int g, int t)
{
#pragma unroll
    for (int mt=0;mt<2;mt++){
        int r0 = warp_m*32 + mt*16 + g;
#pragma unroll
        for (int nt=0;nt<NTW;nt++){
            int col = warp_n*(8*NTW) + nt*8 + 2*t;
            float bb0 = BIAS ? bias[col]   : 0.f;
            float bb1 = BIAS ? bias[col+1] : 0.f;
            float v0 = C[mt][nt][0]+bb0, v1 = C[mt][nt][1]+bb1;
            float v2 = C[mt][nt][2]+bb0, v3 = C[mt][nt][3]+bb1;
            if (RELU){ v0=fmaxf(v0,0.f); v1=fmaxf(v1,0.f); v2=fmaxf(v2,0.f); v3=fmaxf(v3,0.f); }
            if (CVT){ v0=tf32f(v0); v1=tf32f(v1); v2=tf32f(v2); v3=tf32f(v3); }
            *reinterpret_cast<float2*>(O + r0*ostr + col)     = make_float2(v0,v1);
            *reinterpret_cast<float2*>(O + (r0+8)*ostr + col) = make_float2(v2,v3);
        }
    }
}

__global__ void __launch_bounds__(NTHREADS,1) ac_kernel(
    const float* __restrict__ state_one, const float* __restrict__ act_one,
    const float* __restrict__ state_others, const float* __restrict__ act_others,
    const float* __restrict__ W1, const float* __restrict__ b1,
    const float* __restrict__ W2, const float* __restrict__ b2,
    const float* __restrict__ w3_self,
    const float* __restrict__ We, const float* __restrict__ be,
    const float* __restrict__ Wk, const float* __restrict__ Wq,
    const float* __restrict__ Wv, const float* __restrict__ bv,
    const float* __restrict__ w3_others,
    const float* __restrict__ Wout, const float* __restrict__ bout,
    float* __restrict__ out, int B)
{
    extern __shared__ float sm[];
    float* WVPK = sm + OFF_WVPK;
    float* WSPK = sm + OFF_WSPK;
    float* IN   = sm + OFF_IN;
    float* ACT2 = sm + OFF_ACT2;
    float* X1   = sm + OFF_X1;
    float* BIA  = sm + OFF_BIAS;
    float* SMAL = sm + OFF_AL;
    float* SMP  = sm + OFF_P;
    float* RED  = sm + OFF_RED;

    const int tid = threadIdx.x;
    const int lane = tid & 31;
    const int warp = tid >> 5;
    const int g = lane >> 2, t = lane & 3;
    const int warp_m = warp & 1, warp_n = warp >> 1;
    const int b0 = blockIdx.x * BT;

    // ---- initial staging: self inputs, W1, Wv (persistent), biases ----
    for (int i = tid; i < 64*80; i += NTHREADS){
        int row = i/80, c = i - row*80;
        float v = 0.f;
        if (c < 64) v = state_one[(size_t)(b0+row)*64 + c];
        else if (c < 78) v = act_one[(size_t)(b0+row)*14 + (c-64)];
        IN[row*132 + c] = tf32f(v);
    }
    STAGE_PK(WSPK, 78, 10, 2, W1[k*64 + n]);
    STAGE_PK(WVPK, 128, 16, 4, Wv[((n>>5)*128 + k)*32 + (n&31)]);
    for (int i = tid; i < 1216; i += NTHREADS){
        float v;
        if (i < 64) v = b1[i];
        else if (i < 128) v = b2[i-64];
        else if (i < 256) v = bv[i-128];
        else if (i < 1152) v = be[i-256];
        else v = Wout[i-1152];
        BIA[i] = v;
    }
    __syncthreads();

    // S1: x1 = relu(x @ W1 + b1) -> X1 (stride 68, tf32-rounded)
    {
        float C[2][2][4];
        run_mma<10,2>(IN, 132, WSPK, C, warp_m, warp_n, g, t, lane);
        epi_store<2,true,true,true>(C, X1, 68, BIA, warp_m, warp_n, g, t);
    }
    __syncthreads();

    // S4: sel = x1 @ Wq_all -> ACT2 (full fp32, temp)
    STAGE_PK(WSPK, 64, 8, 4, Wq[((n>>5)*64 + k)*32 + (n&31)]);
    __syncthreads();
    {
        float C[2][4][4];
        run_mma<8,4>(X1, 68, WSPK, C, warp_m, warp_n, g, t, lane);
        epi_store<4,false,false,false>(C, ACT2, 132, nullptr, warp_m, warp_n, g, t);
    }
    __syncthreads();

    // sel -> registers; thread role (h = tid/64, b = tid%64)
    const int hh = tid >> 6, bb = tid & 63;
    float selr[32];
    {
        const float* sp = ACT2 + bb*132 + hh*32;
#pragma unroll
        for (int i = 0; i < 8; i++){
            float4 v = *reinterpret_cast<const float4*>(sp + i*4);
            selr[i*4+0]=v.x; selr[i*4+1]=v.y; selr[i*4+2]=v.z; selr[i*4+3]=v.w;
        }
    }
    __syncthreads();

    // S2: x2 = relu(x1 @ W2 + b2) -> ACT2 (stride 132, tf32)
    STAGE_PK(WSPK, 64, 8, 2, W2[k*64 + n]);
    __syncthreads();
    {
        float C[2][2][4];
        run_mma<8,2>(X1, 68, WSPK, C, warp_m, warp_n, g, t, lane);
        epi_store<2,true,true,true>(C, ACT2, 132, BIA+64, warp_m, warp_n, g, t);
    }
    __syncthreads();

    // S3: x3_self = x2 @ w3_self -> X1 (full fp32)
    STAGE_PK(WSPK, 64, 8, 2, w3_self[k*64 + n]);
    __syncthreads();
    {
        float C[2][2][4];
        run_mma<8,2>(ACT2, 132, WSPK, C, warp_m, warp_n, g, t, lane);
        epi_store<2,false,false,false>(C, X1, 68, nullptr, warp_m, warp_n, g, t);
    }

    // online softmax state + ov accumulators
    float m_run = -1e30f, s_run = 0.f;
    float ov[2][4][4];
#pragma unroll
    for (int mt=0;mt<2;mt++)
#pragma unroll
        for (int nt=0;nt<4;nt++)
#pragma unroll
            for (int j=0;j<4;j++) ov[mt][nt][j]=0.f;

    // ---- agent loop ----
    for (int a = 0; a < 7; a++){
        __syncthreads();
        // agent inputs -> IN ; We[a] -> WSPK
        for (int i = tid; i < 64*88; i += NTHREADS){
            int row = i/88, c = i - row*88;
            float v = 0.f;
            if (c < 64) v = state_others[((size_t)a*B + b0+row)*64 + c];
            else if (c < 82) v = act_others[((size_t)a*B + b0+row)*18 + (c-64)];
            IN[row*132 + c] = tf32f(v);
        }
        STAGE_PK(WSPK, 82, 11, 4, We[(size_t)a*82*128 + k*128 + n]);
        __syncthreads();
        // enc = relu(inp @ We + be) -> ACT2 (tf32)
        {
            float C[2][4][4];
            run_mma<11,4>(IN, 132, WSPK, C, warp_m, warp_n, g, t, lane);
            epi_store<4,true,true,true>(C, ACT2, 132, BIA+256+a*128, warp_m, warp_n, g, t);
        }
        __syncthreads();
        // keys = enc @ Wk_all -> IN (full fp32)
        STAGE_PK(WSPK, 128, 16, 4, Wk[((n>>5)*128 + k)*32 + (n&31)]);
        __syncthreads();
        {
            float C[2][4][4];
            run_mma<16,4>(ACT2, 132, WSPK, C, warp_m, warp_n, g, t, lane);
            epi_store<4,false,false,false>(C, IN, 132, nullptr, warp_m, warp_n, g, t);
        }
        __syncthreads();
        // logits + online softmax (thread (hh,bb))
        {
            const float* kp = IN + bb*132 + hh*32;
            float acc = 0.f;
#pragma unroll
            for (int i = 0; i < 8; i++){
                float4 kk = *reinterpret_cast<const float4*>(kp + i*4);
                acc = fmaf(selr[i*4+0], kk.x, acc);
                acc = fmaf(selr[i*4+1], kk.y, acc);
                acc = fmaf(selr[i*4+2], kk.z, acc);
                acc = fmaf(selr[i*4+3], kk.w, acc);
            }
            float lg = acc * LSCALE;
            float mn = fmaxf(m_run, lg);
            float alv = __expf(m_run - mn);
            float pv  = __expf(lg - mn);
            s_run = s_run*alv + pv;
            m_run = mn;
            SMAL[tid] = alv;
            SMP[tid]  = pv;
        }
        __syncthreads();
        // vals = relu(enc @ Wv_all + bv); ov = ov*alpha + p*vals (frag regs)
        {
            float C[2][4][4];
            run_mma<16,4>(ACT2, 132, WVPK, C, warp_m, warp_n, g, t, lane);
#pragma unroll
            for (int mt=0;mt<2;mt++){
                int r0 = warp_m*32 + mt*16 + g, r1 = r0 + 8;
#pragma unroll
                for (int nt=0;nt<4;nt++){
                    int col = warp_n*32 + nt*8 + 2*t;
                    int h = col >> 5;
                    float bv0 = BIA[128+col], bv1 = BIA[128+col+1];
                    float a0 = SMAL[h*64+r0], p0 = SMP[h*64+r0];
                    float a1 = SMAL[h*64+r1], p1 = SMP[h*64+r1];
                    float v0 = fmaxf(C[mt][nt][0]+bv0, 0.f);
                    float v1 = fmaxf(C[mt][nt][1]+bv1, 0.f);
                    float v2 = fmaxf(C[mt][nt][2]+bv0, 0.f);
                    float v3 = fmaxf(C[mt][nt][3]+bv1, 0.f);
                    ov[mt][nt][0] = ov[mt][nt][0]*a0 + p0*v0;
                    ov[mt][nt][1] = ov[mt][nt][1]*a0 + p0*v1;
                    ov[mt][nt][2] = ov[mt][nt][2]*a1 + p1*v2;
                    ov[mt][nt][3] = ov[mt][nt][3]*a1 + p1*v3;
                }
            }
        }
    }

    // publish softmax denominators
    __syncthreads();
    SMAL[tid] = s_run;
    __syncthreads();

    // x2_others = ov / s -> IN (tf32)
#pragma unroll
    for (int mt=0;mt<2;mt++){
        int r0 = warp_m*32 + mt*16 + g, r1 = r0 + 8;
#pragma unroll
        for (int nt=0;nt<4;nt++){
            int col = warp_n*32 + nt*8 + 2*t;
            int h = col >> 5;
            float i0 = 1.f / SMAL[h*64+r0];
            float i1 = 1.f / SMAL[h*64+r1];
            *reinterpret_cast<float2*>(IN + r0*132 + col) =
                make_float2(tf32f(ov[mt][nt][0]*i0), tf32f(ov[mt][nt][1]*i0));
            *reinterpret_cast<float2*>(IN + r1*132 + col) =
                make_float2(tf32f(ov[mt][nt][2]*i1), tf32f(ov[mt][nt][3]*i1));
        }
    }
    STAGE_PK(WSPK, 128, 16, 2, w3_others[k*64 + n]);
    __syncthreads();

    // S8: x3o = x2o @ w3_others; x3 = relu(x3_self + x3o); dot Wout
    {
        float C[2][2][4];
        run_mma<16,2>(IN, 132, WSPK, C, warp_m, warp_n, g, t, lane);
        float prow[2][2] = {{0.f,0.f},{0.f,0.f}};
#pragma unroll
        for (int mt=0;mt<2;mt++){
            int r0 = warp_m*32 + mt*16 + g, r1 = r0 + 8;
#pragma unroll
            for (int nt=0;nt<2;nt++){
                int col = warp_n*16 + nt*8 + 2*t;
                float w0 = BIA[1152+col], w1 = BIA[1152+col+1];
                float x0 = fmaxf(C[mt][nt][0] + X1[r0*68+col],   0.f);
                float x1v= fmaxf(C[mt][nt][1] + X1[r0*68+col+1], 0.f);
                float x2 = fmaxf(C[mt][nt][2] + X1[r1*68+col],   0.f);
                float x3 = fmaxf(C[mt][nt][3] + X1[r1*68+col+1], 0.f);
                prow[mt][0] += x0*w0 + x1v*w1;
                prow[mt][1] += x2*w0 + x3*w1;
            }
        }
#pragma unroll
        for (int off = 1; off <= 2; off <<= 1){
#pragma unroll
            for (int mt=0;mt<2;mt++){
                prow[mt][0] += __shfl_xor_sync(0xffffffffu, prow[mt][0], off);
                prow[mt][1] += __shfl_xor_sync(0xffffffffu, prow[mt][1], off);
            }
        }
        if (t == 0){
#pragma unroll
            for (int mt=0;mt<2;mt++){
                int r0 = warp_m*32 + mt*16 + g;
                RED[warp_n*64 + r0]     = prow[mt][0];
                RED[warp_n*64 + r0 + 8] = prow[mt][1];
            }
        }
    }
    __syncthreads();
    if (tid < 64){
        float o = RED[tid] + RED[64+tid] + RED[128+tid] + RED[192+tid] + bout[0];
        out[b0 + tid] = o;
    }
}

extern "C" void kernel_launch(void* const* d_in, const int* in_sizes, int n_in,
                              void* d_out, int out_size)
{
    const float* state_one    = (const float*)d_in[0];
    const float* act_one      = (const float*)d_in[1];
    const float* state_others = (const float*)d_in[2];
    const float* act_others   = (const float*)d_in[3];
    const float* W1   = (const float*)d_in[4];
    const float* b1   = (const float*)d_in[5];
    const float* W2   = (const float*)d_in[6];
    const float* b2   = (const float*)d_in[7];
    const float* w3s  = (const float*)d_in[8];
    const float* We   = (const float*)d_in[9];
    const float* be   = (const float*)d_in[10];
    const float* Wk   = (const float*)d_in[11];
    const float* Wq   = (const float*)d_in[12];
    const float* Wv   = (const float*)d_in[13];
    const float* bv   = (const float*)d_in[14];
    const float* w3o  = (const float*)d_in[15];
    const float* Wout = (const float*)d_in[16];
    const float* bout = (const float*)d_in[17];
    float* out = (float*)d_out;

    int B = in_sizes[0] / 64;
    int smem_bytes = SMEM_FLOATS * sizeof(float);
    cudaFuncSetAttribute(ac_kernel, cudaFuncAttributeMaxDynamicSharedMemorySize, smem_bytes);
    dim3 grid(B / BT), block(NTHREADS);
    ac_kernel<<<grid, block, smem_bytes>>>(
        state_one, act_one, state_others, act_others,
        W1, b1, W2, b2, w3s, We, be, Wk, Wq, Wv, bv, w3o, Wout, bout, out, B);
}

// round 6
// speedup vs baseline: 2.7853x; 2.1068x over previous
#include <cuda_runtime.h>
#include <cstdint>

#define NTHREADS 512
#define BT 64
#define LSCALE 0.17677669529663687f  // 1/sqrt(32)

// ---------------- packed-weight device buffer (floats) ----------------
#define PK_W1   0        // KS=10 NTW=2 -> 5120
#define PK_WQ   5120     // KS=8  NTW=4 -> 8192
#define PK_W2   13312    // KS=8  NTW=2 -> 4096
#define PK_W3S  17408    // KS=8  NTW=2 -> 4096
#define PK_W3O  21504    // KS=16 NTW=2 -> 8192
#define PK_WK   29696    // KS=16 NTW=4 -> 16384
#define PK_WV   46080    // KS=16 NTW=4 -> 16384
#define PK_WE   62464    // 7 * (KS=11 NTW=4 -> 11264) = 78848
#define PK_TOTAL 141312
__device__ float g_pk[PK_TOTAL];

// ---------------- smem layout (floats) ----------------
#define OFF_WVPK  0        // Wv packed resident, 16384
#define OFF_WSPK  16384    // staging (W1+Wq | W2+w3s | We | Wk | w3o), 16384
#define OFF_IN    32768    // [64][132] inputs / keys / x2_others
#define OFF_ACT2  41216    // [64][132] sel / x2 / enc
#define OFF_X1    49664    // [64][68] x1
#define OFF_BIAS  54016    // b1(64) b2(64) bv(128) be(896) Wout(64) = 1216
#define OFF_AL    55232    // [4][64]
#define OFF_P     55488    // [4][64]
#define OFF_RED   55744    // [4][64]
#define SMEM_FLOATS 56000  // 224000 bytes

__device__ __forceinline__ float tf32f(float x){
    uint32_t u; asm("cvt.rna.tf32.f32 %0, %1;" : "=r"(u) : "f"(x));
    return __uint_as_float(u);
}

// ================= prep kernel: pack weights fragment-major =================
// dst[i], i = (((ks*4+nw)*2+half)*32+lane)*NTW + tile
// k = ks*8 + lane%4 + half*4 ; n = nw*8*NTW + tile*8 + lane/4
#define PACK_REGION(DST, KS, NTW, KACT, SRCEXPR) do {                      \
    int SZ_ = (KS)*4*2*32*(NTW);                                           \
    for (int i_ = t0; i_ < SZ_; i_ += NT){                                 \
        int tile = i_ % (NTW); int r_ = i_ / (NTW);                        \
        int lane_ = r_ & 31; r_ >>= 5;                                     \
        int half_ = r_ & 1;  r_ >>= 1;                                     \
        int nw_ = r_ & 3;    int ks_ = r_ >> 2;                            \
        int k = ks_*8 + (lane_ & 3) + half_*4;                             \
        int n = nw_*8*(NTW) + tile*8 + (lane_ >> 2);                       \
        float v_ = 0.f;                                                    \
        if (k < (KACT)) { v_ = (SRCEXPR); }                                \
        (DST)[i_] = tf32f(v_);                                             \
    } } while(0)

__global__ void prep_kernel(const float* __restrict__ W1, const float* __restrict__ Wq,
                            const float* __restrict__ W2, const float* __restrict__ w3s,
                            const float* __restrict__ w3o, const float* __restrict__ Wk,
                            const float* __restrict__ Wv, const float* __restrict__ We){
    int t0 = blockIdx.x*blockDim.x + threadIdx.x;
    int NT = gridDim.x*blockDim.x;
    PACK_REGION(g_pk+PK_W1, 10, 2, 78, W1[k*64+n]);
    PACK_REGION(g_pk+PK_WQ,  8, 4, 64, Wq[(n>>5)*2048 + k*32 + (n&31)]);
    PACK_REGION(g_pk+PK_W2,  8, 2, 64, W2[k*64+n]);
    PACK_REGION(g_pk+PK_W3S, 8, 2, 64, w3s[k*64+n]);
    PACK_REGION(g_pk+PK_W3O,16, 2,128, w3o[k*64+n]);
    PACK_REGION(g_pk+PK_WK, 16, 4,128, Wk[(n>>5)*4096 + k*32 + (n&31)]);
    PACK_REGION(g_pk+PK_WV, 16, 4,128, Wv[(n>>5)*4096 + k*32 + (n&31)]);
    for (int a = 0; a < 7; a++){
        PACK_REGION(g_pk+PK_WE + a*11264, 11, 4, 82, We[a*82*128 + k*128 + n]);
    }
}

// ================= main kernel helpers =================
__device__ __forceinline__ void cp_async16(float* dst, const float* src){
    uint32_t s = (uint32_t)__cvta_generic_to_shared(dst);
    asm volatile("cp.async.cg.shared.global [%0], [%1], 16;" :: "r"(s), "l"(src));
}
__device__ __forceinline__ void cp_commit_wait(){
    asm volatile("cp.async.commit_group;");
    asm volatile("cp.async.wait_group 0;" ::: "memory");
}
__device__ __forceinline__ void copy_pk(float* dst, const float* src, int n, int tid){
    for (int i = tid*4; i < n; i += NTHREADS*4) cp_async16(dst+i, src+i);
}

__device__ __forceinline__ void mma8(float* c, const uint32_t* a, uint32_t b0, uint32_t b1){
    asm volatile("mma.sync.aligned.m16n8k8.row.col.f32.tf32.tf32.f32 "
        "{%0,%1,%2,%3},{%4,%5,%6,%7},{%8,%9},{%0,%1,%2,%3};"
        : "+f"(c[0]),"+f"(c[1]),"+f"(c[2]),"+f"(c[3])
        : "r"(a[0]),"r"(a[1]),"r"(a[2]),"r"(a[3]),"r"(b0),"r"(b1));
}

// warp tile: 16 rows (warp_m) x 8*NTW cols (warp_n); C[NTW][4]
template<int KS, int NTW>
__device__ __forceinline__ void run_mma(const float* __restrict__ A, int astr,
                                        const float* __restrict__ Bpk,
                                        float (&C)[NTW][4],
                                        int warp_m, int warp_n, int g, int t, int lane)
{
#pragma unroll
    for (int nt=0;nt<NTW;nt++)
#pragma unroll
        for (int j=0;j<4;j++) C[nt][j]=0.f;
    const float* ap = A + (warp_m*16 + g)*astr + t;
#pragma unroll
    for (int ks=0; ks<KS; ks++){
        uint32_t a[4];
        a[0] = __float_as_uint(ap[ks*8]);
        a[1] = __float_as_uint(ap[8*astr + ks*8]);
        a[2] = __float_as_uint(ap[ks*8 + 4]);
        a[3] = __float_as_uint(ap[8*astr + ks*8 + 4]);
        const float* bp = Bpk + ((size_t)((ks*4 + warp_n)*2)*32 + lane)*NTW;
        uint32_t b0[NTW], b1[NTW];
        if constexpr (NTW==4){
            float4 x = *reinterpret_cast<const float4*>(bp);
            float4 y = *reinterpret_cast<const float4*>(bp + 32*4);
            b0[0]=__float_as_uint(x.x); b0[1]=__float_as_uint(x.y);
            b0[2]=__float_as_uint(x.z); b0[3]=__float_as_uint(x.w);
            b1[0]=__float_as_uint(y.x); b1[1]=__float_as_uint(y.y);
            b1[2]=__float_as_uint(y.z); b1[3]=__float_as_uint(y.w);
        } else {
            float2 x = *reinterpret_cast<const float2*>(bp);
            float2 y = *reinterpret_cast<const float2*>(bp + 32*2);
            b0[0]=__float_as_uint(x.x); b0[1]=__float_as_uint(x.y);
            b1[0]=__float_as_uint(y.x); b1[1]=__float_as_uint(y.y);
        }
#pragma unroll
        for (int nt=0;nt<NTW;nt++)
            mma8(C[nt], a, b0[nt], b1[nt]);
    }
}

template<int NTW, bool RELU, bool BIAS, bool CVT>
__device__ __forceinline__ void epi_store(float (&C)[NTW][4], float* __restrict__ O, int ostr,
                                          const float* __restrict__ bias,
                                          int warp_m, int warp_n, int g, int t)
{
    int r0 = warp_m*16 + g;
#pragma unroll
    for (int nt=0;nt<NTW;nt++){
        int col = warp_n*(8*NTW) + nt*8 + 2*t;
        float bb0 = BIAS ? bias[col]   : 0.f;
        float bb1 = BIAS ? bias[col+1] : 0.f;
        float v0 = C[nt][0]+bb0, v1 = C[nt][1]+bb1;
        float v2 = C[nt][2]+bb0, v3 = C[nt][3]+bb1;
        if (RELU){ v0=fmaxf(v0,0.f); v1=fmaxf(v1,0.f); v2=fmaxf(v2,0.f); v3=fmaxf(v3,0.f); }
        if (CVT){ v0=tf32f(v0); v1=tf32f(v1); v2=tf32f(v2); v3=tf32f(v3); }
        *reinterpret_cast<float2*>(O + r0*ostr + col)     = make_float2(v0,v1);
        *reinterpret_cast<float2*>(O + (r0+8)*ostr + col) = make_float2(v2,v3);
    }
}

__global__ void __launch_bounds__(NTHREADS,1) ac_kernel(
    const float* __restrict__ state_one, const float* __restrict__ act_one,
    const float* __restrict__ state_others, const float* __restrict__ act_others,
    const float* __restrict__ b1, const float* __restrict__ b2,
    const float* __restrict__ be, const float* __restrict__ bv,
    const float* __restrict__ Wout, const float* __restrict__ bout,
    float* __restrict__ out, int B)
{
    extern __shared__ float sm[];
    float* WVPK = sm + OFF_WVPK;
    float* WSPK = sm + OFF_WSPK;
    float* IN   = sm + OFF_IN;
    float* ACT2 = sm + OFF_ACT2;
    float* X1   = sm + OFF_X1;
    float* BIA  = sm + OFF_BIAS;
    float* SMAL = sm + OFF_AL;
    float* SMP  = sm + OFF_P;
    float* RED  = sm + OFF_RED;

    const int tid = threadIdx.x;
    const int lane = tid & 31;
    const int warp = tid >> 5;
    const int g = lane >> 2, t = lane & 3;
    const int warp_m = warp & 3, warp_n = warp >> 2;
    const int b0 = blockIdx.x * BT;

    // ---- initial staging: Wv resident + W1|Wq, self inputs, biases ----
    copy_pk(WVPK, g_pk+PK_WV, 16384, tid);
    copy_pk(WSPK, g_pk+PK_W1, 13312, tid);   // W1 @0, Wq @5120
    for (int i = tid; i < 64*20; i += NTHREADS){
        int row = i/20, c4 = i - row*20; int c = c4*4;
        float4 v;
        if (c4 < 16){
            v = *reinterpret_cast<const float4*>(state_one + (size_t)(b0+row)*64 + c);
        } else {
            const float* ap = act_one + (size_t)(b0+row)*14;
            int j = c - 64;
            v.x = (j   < 14) ? ap[j]   : 0.f;
            v.y = (j+1 < 14) ? ap[j+1] : 0.f;
            v.z = (j+2 < 14) ? ap[j+2] : 0.f;
            v.w = (j+3 < 14) ? ap[j+3] : 0.f;
        }
        v.x=tf32f(v.x); v.y=tf32f(v.y); v.z=tf32f(v.z); v.w=tf32f(v.w);
        *reinterpret_cast<float4*>(IN + row*132 + c) = v;
    }
    for (int i = tid; i < 1216; i += NTHREADS){
        float v;
        if (i < 64) v = b1[i];
        else if (i < 128) v = b2[i-64];
        else if (i < 256) v = bv[i-128];
        else if (i < 1152) v = be[i-256];
        else v = Wout[i-1152];
        BIA[i] = v;
    }
    cp_commit_wait();
    __syncthreads();

    // S1: x1 = relu(x @ W1 + b1) -> X1 (stride 68, tf32)
    {
        float C[2][4];
        run_mma<10,2>(IN, 132, WSPK, C, warp_m, warp_n, g, t, lane);
        epi_store<2,true,true,true>(C, X1, 68, BIA, warp_m, warp_n, g, t);
    }
    __syncthreads();

    // S4: sel = x1 @ Wq_all -> ACT2 (fp32)
    {
        float C[4][4];
        run_mma<8,4>(X1, 68, WSPK+5120, C, warp_m, warp_n, g, t, lane);
        epi_store<4,false,false,false>(C, ACT2, 132, nullptr, warp_m, warp_n, g, t);
    }
    __syncthreads();

    // sel -> regs; role: h = tid>>7, b = (tid>>1)&63, half = tid&1 (16 d's each)
    const int hh = tid >> 7, bq = (tid >> 1) & 63, hf = tid & 1;
    float selr[16];
    {
        const float* sp = ACT2 + bq*132 + hh*32 + hf*16;
#pragma unroll
        for (int i = 0; i < 4; i++){
            float4 v = *reinterpret_cast<const float4*>(sp + i*4);
            selr[i*4+0]=v.x; selr[i*4+1]=v.y; selr[i*4+2]=v.z; selr[i*4+3]=v.w;
        }
    }
    copy_pk(WSPK, g_pk+PK_W2, 8192, tid);  // W2 @0, w3s @4096
    cp_commit_wait();
    __syncthreads();

    // S2: x2 = relu(x1 @ W2 + b2) -> ACT2 (tf32)
    {
        float C[2][4];
        run_mma<8,2>(X1, 68, WSPK, C, warp_m, warp_n, g, t, lane);
        epi_store<2,true,true,true>(C, ACT2, 132, BIA+64, warp_m, warp_n, g, t);
    }
    __syncthreads();

    // S3: x3_self = x2 @ w3_self -> registers (same frag map as final stage)
    float x3s[2][4];
    run_mma<8,2>(ACT2, 132, WSPK+4096, x3s, warp_m, warp_n, g, t, lane);
    __syncthreads();

    float m_run = -1e30f, s_run = 0.f;
    float ov[4][4];
#pragma unroll
    for (int nt=0;nt<4;nt++)
#pragma unroll
        for (int j=0;j<4;j++) ov[nt][j]=0.f;

    // ---- agent loop ----
    for (int a = 0; a < 7; a++){
        // stage agent inputs + We[a]
        copy_pk(WSPK, g_pk+PK_WE + a*11264, 11264, tid);
        for (int i = tid; i < 64*22; i += NTHREADS){
            int row = i/22, c4 = i - row*22; int c = c4*4;
            float4 v;
            if (c4 < 16){
                v = *reinterpret_cast<const float4*>(state_others + ((size_t)a*B + b0+row)*64 + c);
            } else {
                const float* ap = act_others + ((size_t)a*B + b0+row)*18;
                int j = c - 64;
                v.x = (j   < 18) ? ap[j]   : 0.f;
                v.y = (j+1 < 18) ? ap[j+1] : 0.f;
                v.z = (j+2 < 18) ? ap[j+2] : 0.f;
                v.w = (j+3 < 18) ? ap[j+3] : 0.f;
            }
            v.x=tf32f(v.x); v.y=tf32f(v.y); v.z=tf32f(v.z); v.w=tf32f(v.w);
            *reinterpret_cast<float4*>(IN + row*132 + c) = v;
        }
        cp_commit_wait();
        __syncthreads();

        // enc = relu(inp @ We + be) -> ACT2 (tf32)
        {
            float C[4][4];
            run_mma<11,4>(IN, 132, WSPK, C, warp_m, warp_n, g, t, lane);
            epi_store<4,true,true,true>(C, ACT2, 132, BIA+256+a*128, warp_m, warp_n, g, t);
        }
        __syncthreads();

        copy_pk(WSPK, g_pk+PK_WK, 16384, tid);
        cp_commit_wait();
        __syncthreads();

        // keys -> IN ; vals mma -> Cv regs (epilogue deferred)
        float Cv[4][4];
        {
            float C[4][4];
            run_mma<16,4>(ACT2, 132, WSPK, C, warp_m, warp_n, g, t, lane);
            epi_store<4,false,false,false>(C, IN, 132, nullptr, warp_m, warp_n, g, t);
        }
        run_mma<16,4>(ACT2, 132, WVPK, Cv, warp_m, warp_n, g, t, lane);
        __syncthreads();

        // logits + online softmax: thread (hh,bq,hf), 16-d partial + pair shuffle
        {
            const float* kp = IN + bq*132 + hh*32 + hf*16;
            float part = 0.f;
#pragma unroll
            for (int i = 0; i < 4; i++){
                float4 kk = *reinterpret_cast<const float4*>(kp + i*4);
                part = fmaf(selr[i*4+0], kk.x, part);
                part = fmaf(selr[i*4+1], kk.y, part);
                part = fmaf(selr[i*4+2], kk.z, part);
                part = fmaf(selr[i*4+3], kk.w, part);
            }
            float full = part + __shfl_xor_sync(0xffffffffu, part, 1);
            float lg = full * LSCALE;
            float mn = fmaxf(m_run, lg);
            float alv = __expf(m_run - mn);
            float pv  = __expf(lg - mn);
            s_run = s_run*alv + pv;
            m_run = mn;
            if (!hf){ SMAL[hh*64+bq] = alv; SMP[hh*64+bq] = pv; }
        }
        __syncthreads();

        // vals epilogue + ov update (regs)
        {
            int r0 = warp_m*16 + g, r1 = r0 + 8;
#pragma unroll
            for (int nt=0;nt<4;nt++){
                int col = warp_n*32 + nt*8 + 2*t;
                int h = col >> 5;
                float bv0 = BIA[128+col], bv1 = BIA[128+col+1];
                float a0 = SMAL[h*64+r0], p0 = SMP[h*64+r0];
                float a1 = SMAL[h*64+r1], p1 = SMP[h*64+r1];
                float v0 = fmaxf(Cv[nt][0]+bv0, 0.f);
                float v1 = fmaxf(Cv[nt][1]+bv1, 0.f);
                float v2 = fmaxf(Cv[nt][2]+bv0, 0.f);
                float v3 = fmaxf(Cv[nt][3]+bv1, 0.f);
                ov[nt][0] = ov[nt][0]*a0 + p0*v0;
                ov[nt][1] = ov[nt][1]*a0 + p0*v1;
                ov[nt][2] = ov[nt][2]*a1 + p1*v2;
                ov[nt][3] = ov[nt][3]*a1 + p1*v3;
            }
        }
    }

    __syncthreads();
    if (!hf) SMAL[hh*64+bq] = s_run;
    copy_pk(WSPK, g_pk+PK_W3O, 8192, tid);
    __syncthreads();

    // x2_others = ov / s -> IN (tf32)
    {
        int r0 = warp_m*16 + g, r1 = r0 + 8;
#pragma unroll
        for (int nt=0;nt<4;nt++){
            int col = warp_n*32 + nt*8 + 2*t;
            int h = col >> 5;
            float i0 = 1.f / SMAL[h*64+r0];
            float i1 = 1.f / SMAL[h*64+r1];
            *reinterpret_cast<float2*>(IN + r0*132 + col) =
                make_float2(tf32f(ov[nt][0]*i0), tf32f(ov[nt][1]*i0));
            *reinterpret_cast<float2*>(IN + r1*132 + col) =
                make_float2(tf32f(ov[nt][2]*i1), tf32f(ov[nt][3]*i1));
        }
    }
    cp_commit_wait();
    __syncthreads();

    // S8: x3o = x2o @ w3_others; x3 = relu(x3_self + x3o); dot Wout; reduce
    {
        float C[2][4];
        run_mma<16,2>(IN, 132, WSPK, C, warp_m, warp_n, g, t, lane);
        int r0 = warp_m*16 + g;
        float pr0 = 0.f, pr1 = 0.f;
#pragma unroll
        for (int nt=0;nt<2;nt++){
            int col = warp_n*16 + nt*8 + 2*t;
            float w0 = BIA[1152+col], w1 = BIA[1152+col+1];
            pr0 += fmaxf(C[nt][0]+x3s[nt][0], 0.f)*w0 + fmaxf(C[nt][1]+x3s[nt][1], 0.f)*w1;
            pr1 += fmaxf(C[nt][2]+x3s[nt][2], 0.f)*w0 + fmaxf(C[nt][3]+x3s[nt][3], 0.f)*w1;
        }
        pr0 += __shfl_xor_sync(0xffffffffu, pr0, 1);
        pr1 += __shfl_xor_sync(0xffffffffu, pr1, 1);
        pr0 += __shfl_xor_sync(0xffffffffu, pr0, 2);
        pr1 += __shfl_xor_sync(0xffffffffu, pr1, 2);
        if (t == 0){
            RED[warp_n*64 + r0]     = pr0;
            RED[warp_n*64 + r0 + 8] = pr1;
        }
    }
    __syncthreads();
    if (tid < 64){
        out[b0 + tid] = RED[tid] + RED[64+tid] + RED[128+tid] + RED[192+tid] + bout[0];
    }
}

extern "C" void kernel_launch(void* const* d_in, const int* in_sizes, int n_in,
                              void* d_out, int out_size)
{
    const float* state_one    = (const float*)d_in[0];
    const float* act_one      = (const float*)d_in[1];
    const float* state_others = (const float*)d_in[2];
    const float* act_others   = (const float*)d_in[3];
    const float* W1   = (const float*)d_in[4];
    const float* b1   = (const float*)d_in[5];
    const float* W2   = (const float*)d_in[6];
    const float* b2   = (const float*)d_in[7];
    const float* w3s  = (const float*)d_in[8];
    const float* We   = (const float*)d_in[9];
    const float* be   = (const float*)d_in[10];
    const float* Wk   = (const float*)d_in[11];
    const float* Wq   = (const float*)d_in[12];
    const float* Wv   = (const float*)d_in[13];
    const float* bv   = (const float*)d_in[14];
    const float* w3o  = (const float*)d_in[15];
    const float* Wout = (const float*)d_in[16];
    const float* bout = (const float*)d_in[17];
    float* out = (float*)d_out;

    int B = in_sizes[0] / 64;

    prep_kernel<<<138, 256>>>(W1, Wq, W2, w3s, w3o, Wk, Wv, We);

    int smem_bytes = SMEM_FLOATS * sizeof(float);
    cudaFuncSetAttribute(ac_kernel, cudaFuncAttributeMaxDynamicSharedMemorySize, smem_bytes);
    ac_kernel<<<B/BT, NTHREADS, smem_bytes>>>(
        state_one, act_one, state_others, act_others,
        b1, b2, be, bv, Wout, bout, out, B);
}

// round 7
// speedup vs baseline: 3.4225x; 1.2288x over previous
#include <cuda_runtime.h>
#include <cstdint>

#define NTHREADS 512
#define BT 64
#define LSCALE 0.17677669529663687f  // 1/sqrt(32)
#define INSTR 92

// ---------------- packed-weight device buffer (floats) ----------------
#define PK_W1   0        // KS=10 NTW=2 -> 5120
#define PK_WQ   5120     // KS=8  NTW=4 -> 8192
#define PK_W2   13312    // KS=8  NTW=2 -> 4096
#define PK_W3S  17408    // KS=8  NTW=2 -> 4096
#define PK_W3O  21504    // KS=16 NTW=2 -> 8192
#define PK_WK   29696    // KS=16 NTW=4 -> 16384
#define PK_WV   46080    // KS=16 NTW=4 -> 16384
#define PK_WE   62464    // 7 * 11264 = 78848
#define PK_TOTAL 141312
__device__ float g_pk[PK_TOTAL];

// ---------------- smem layout (floats) ----------------
#define OFF_WVPK 0        // Wv packed resident (16384)
#define OFF_WSPK 16384    // We staging (11264)
#define OFF_IN   27648    // [64][92] inputs (5888)
#define OFF_ACT2 33536    // [64][132] sel-temp/x2/enc/x2_others (8448)
#define OFF_X1   41984    // [64][68] x1 (4352)
#define OFF_BIA  46336    // b1(64) b2(64) bv(128) Wout(64) = 320
#define OFF_RED  46656    // 256
#define SMEM_FLOATS 46912 // 187648 bytes

__device__ __forceinline__ float tf32f(float x){
    uint32_t u; asm("cvt.rna.tf32.f32 %0, %1;" : "=r"(u) : "f"(x));
    return __uint_as_float(u);
}

// ================= prep kernel: pack weights fragment-major =================
#define PACK_REGION(DST, KS, NTW, KACT, SRCEXPR) do {                      \
    int SZ_ = (KS)*4*2*32*(NTW);                                           \
    for (int i_ = t0; i_ < SZ_; i_ += NT){                                 \
        int tile = i_ % (NTW); int r_ = i_ / (NTW);                        \
        int lane_ = r_ & 31; r_ >>= 5;                                     \
        int half_ = r_ & 1;  r_ >>= 1;                                     \
        int nw_ = r_ & 3;    int ks_ = r_ >> 2;                            \
        int k = ks_*8 + (lane_ & 3) + half_*4;                             \
        int n = nw_*8*(NTW) + tile*8 + (lane_ >> 2);                       \
        float v_ = 0.f;                                                    \
        if (k < (KACT)) { v_ = (SRCEXPR); }                                \
        (DST)[i_] = tf32f(v_);                                             \
    } } while(0)

__global__ void prep_kernel(const float* __restrict__ W1, const float* __restrict__ Wq,
                            const float* __restrict__ W2, const float* __restrict__ w3s,
                            const float* __restrict__ w3o, const float* __restrict__ Wk,
                            const float* __restrict__ Wv, const float* __restrict__ We){
    int t0 = blockIdx.x*blockDim.x + threadIdx.x;
    int NT = gridDim.x*blockDim.x;
    PACK_REGION(g_pk+PK_W1, 10, 2, 78, W1[k*64+n]);
    PACK_REGION(g_pk+PK_WQ,  8, 4, 64, Wq[(n>>5)*2048 + k*32 + (n&31)]);
    PACK_REGION(g_pk+PK_W2,  8, 2, 64, W2[k*64+n]);
    PACK_REGION(g_pk+PK_W3S, 8, 2, 64, w3s[k*64+n]);
    PACK_REGION(g_pk+PK_W3O,16, 2,128, w3o[k*64+n]);
    PACK_REGION(g_pk+PK_WK, 16, 4,128, Wk[(n>>5)*4096 + k*32 + (n&31)]);
    PACK_REGION(g_pk+PK_WV, 16, 4,128, Wv[(n>>5)*4096 + k*32 + (n&31)]);
    for (int a = 0; a < 7; a++){
        PACK_REGION(g_pk+PK_WE + a*11264, 11, 4, 82, We[a*82*128 + k*128 + n]);
    }
}

// ================= main kernel helpers =================
__device__ __forceinline__ void cp_async16(float* dst, const float* src){
    uint32_t s = (uint32_t)__cvta_generic_to_shared(dst);
    asm volatile("cp.async.cg.shared.global [%0], [%1], 16;" :: "r"(s), "l"(src));
}
__device__ __forceinline__ void cp_commit(){
    asm volatile("cp.async.commit_group;");
}
__device__ __forceinline__ void cp_wait0(){
    asm volatile("cp.async.wait_group 0;" ::: "memory");
}
__device__ __forceinline__ void copy_pk(float* dst, const float* src, int n, int tid){
    for (int i = tid*4; i < n; i += NTHREADS*4) cp_async16(dst+i, src+i);
}

__device__ __forceinline__ void mma8(float* c, const uint32_t* a, uint32_t b0, uint32_t b1){
    asm volatile("mma.sync.aligned.m16n8k8.row.col.f32.tf32.tf32.f32 "
        "{%0,%1,%2,%3},{%4,%5,%6,%7},{%8,%9},{%0,%1,%2,%3};"
        : "+f"(c[0]),"+f"(c[1]),"+f"(c[2]),"+f"(c[3])
        : "r"(a[0]),"r"(a[1]),"r"(a[2]),"r"(a[3]),"r"(b0),"r"(b1));
}

// warp tile: 16 rows (warp_m) x 8*NTW cols (warp_n); BG=1 -> B from global (L2)
template<int KS, int NTW, bool BG>
__device__ __forceinline__ void run_mma(const float* __restrict__ A, int astr,
                                        const float* __restrict__ Bpk,
                                        float (&C)[NTW][4],
                                        int warp_m, int warp_n, int g, int t, int lane)
{
#pragma unroll
    for (int nt=0;nt<NTW;nt++)
#pragma unroll
        for (int j=0;j<4;j++) C[nt][j]=0.f;
    const float* ap = A + (warp_m*16 + g)*astr + t;
#pragma unroll
    for (int ks=0; ks<KS; ks++){
        uint32_t a[4];
        a[0] = __float_as_uint(ap[ks*8]);
        a[1] = __float_as_uint(ap[8*astr + ks*8]);
        a[2] = __float_as_uint(ap[ks*8 + 4]);
        a[3] = __float_as_uint(ap[8*astr + ks*8 + 4]);
        const float* bp = Bpk + ((size_t)((ks*4 + warp_n)*2)*32 + lane)*NTW;
        uint32_t b0[NTW], b1[NTW];
        if constexpr (NTW==4){
            float4 x, y;
            if constexpr (BG){
                x = __ldg(reinterpret_cast<const float4*>(bp));
                y = __ldg(reinterpret_cast<const float4*>(bp + 32*4));
            } else {
                x = *reinterpret_cast<const float4*>(bp);
                y = *reinterpret_cast<const float4*>(bp + 32*4);
            }
            b0[0]=__float_as_uint(x.x); b0[1]=__float_as_uint(x.y);
            b0[2]=__float_as_uint(x.z); b0[3]=__float_as_uint(x.w);
            b1[0]=__float_as_uint(y.x); b1[1]=__float_as_uint(y.y);
            b1[2]=__float_as_uint(y.z); b1[3]=__float_as_uint(y.w);
        } else {
            float2 x, y;
            if constexpr (BG){
                x = __ldg(reinterpret_cast<const float2*>(bp));
                y = __ldg(reinterpret_cast<const float2*>(bp + 32*2));
            } else {
                x = *reinterpret_cast<const float2*>(bp);
                y = *reinterpret_cast<const float2*>(bp + 32*2);
            }
            b0[0]=__float_as_uint(x.x); b0[1]=__float_as_uint(x.y);
            b1[0]=__float_as_uint(y.x); b1[1]=__float_as_uint(y.y);
        }
#pragma unroll
        for (int nt=0;nt<NTW;nt++)
            mma8(C[nt], a, b0[nt], b1[nt]);
    }
}

template<int NTW, bool RELU, bool BIAS, bool CVT>
__device__ __forceinline__ void epi_store(float (&C)[NTW][4], float* __restrict__ O, int ostr,
                                          const float* __restrict__ bias,
                                          int warp_m, int warp_n, int g, int t)
{
    int r0 = warp_m*16 + g;
#pragma unroll
    for (int nt=0;nt<NTW;nt++){
        int col = warp_n*(8*NTW) + nt*8 + 2*t;
        float bb0 = BIAS ? bias[col]   : 0.f;
        float bb1 = BIAS ? bias[col+1] : 0.f;
        float v0 = C[nt][0]+bb0, v1 = C[nt][1]+bb1;
        float v2 = C[nt][2]+bb0, v3 = C[nt][3]+bb1;
        if (RELU){ v0=fmaxf(v0,0.f); v1=fmaxf(v1,0.f); v2=fmaxf(v2,0.f); v3=fmaxf(v3,0.f); }
        if (CVT){ v0=tf32f(v0); v1=tf32f(v1); v2=tf32f(v2); v3=tf32f(v3); }
        *reinterpret_cast<float2*>(O + r0*ostr + col)     = make_float2(v0,v1);
        *reinterpret_cast<float2*>(O + (r0+8)*ostr + col) = make_float2(v2,v3);
    }
}

__device__ __forceinline__ void stage_agent(float* IN, const float* __restrict__ so,
                                            const float* __restrict__ ao,
                                            int B, int b0, int a, int tid){
    for (int i = tid; i < 64*22; i += NTHREADS){
        int row = i/22, c4 = i - row*22; int c = c4*4;
        float4 v;
        if (c4 < 16){
            v = *reinterpret_cast<const float4*>(so + ((size_t)a*B + b0+row)*64 + c);
        } else {
            const float* ap = ao + ((size_t)a*B + b0+row)*18;
            int j = c - 64;
            v.x = (j   < 18) ? ap[j]   : 0.f;
            v.y = (j+1 < 18) ? ap[j+1] : 0.f;
            v.z = (j+2 < 18) ? ap[j+2] : 0.f;
            v.w = (j+3 < 18) ? ap[j+3] : 0.f;
        }
        v.x=tf32f(v.x); v.y=tf32f(v.y); v.z=tf32f(v.z); v.w=tf32f(v.w);
        *reinterpret_cast<float4*>(IN + row*INSTR + c) = v;
    }
}

__global__ void __launch_bounds__(NTHREADS,1) ac_kernel(
    const float* __restrict__ state_one, const float* __restrict__ act_one,
    const float* __restrict__ state_others, const float* __restrict__ act_others,
    const float* __restrict__ b1, const float* __restrict__ b2,
    const float* __restrict__ be, const float* __restrict__ bv,
    const float* __restrict__ Wout, const float* __restrict__ bout,
    float* __restrict__ out, int B)
{
    extern __shared__ float sm[];
    float* WVPK = sm + OFF_WVPK;
    float* WSPK = sm + OFF_WSPK;
    float* IN   = sm + OFF_IN;
    float* ACT2 = sm + OFF_ACT2;
    float* X1   = sm + OFF_X1;
    float* BIA  = sm + OFF_BIA;
    float* RED  = sm + OFF_RED;

    const int tid = threadIdx.x;
    const int lane = tid & 31;
    const int warp = tid >> 5;
    const int g = lane >> 2, t = lane & 3;
    const int warp_m = warp & 3, warp_n = warp >> 2;
    const int b0 = blockIdx.x * BT;

    // ---- initial staging: Wv + We[0] via cp.async; self inputs + biases via STS ----
    copy_pk(WVPK, g_pk+PK_WV, 16384, tid);
    copy_pk(WSPK, g_pk+PK_WE, 11264, tid);
    cp_commit();
    for (int i = tid; i < 64*20; i += NTHREADS){
        int row = i/20, c4 = i - row*20; int c = c4*4;
        float4 v;
        if (c4 < 16){
            v = *reinterpret_cast<const float4*>(state_one + (size_t)(b0+row)*64 + c);
        } else {
            const float* ap = act_one + (size_t)(b0+row)*14;
            int j = c - 64;
            v.x = (j   < 14) ? ap[j]   : 0.f;
            v.y = (j+1 < 14) ? ap[j+1] : 0.f;
            v.z = (j+2 < 14) ? ap[j+2] : 0.f;
            v.w = (j+3 < 14) ? ap[j+3] : 0.f;
        }
        v.x=tf32f(v.x); v.y=tf32f(v.y); v.z=tf32f(v.z); v.w=tf32f(v.w);
        *reinterpret_cast<float4*>(IN + row*INSTR + c) = v;
    }
    for (int i = tid; i < 320; i += NTHREADS){
        float v;
        if (i < 64) v = b1[i];
        else if (i < 128) v = b2[i-64];
        else if (i < 256) v = bv[i-128];
        else v = Wout[i-256];
        BIA[i] = v;
    }
    __syncthreads();                                           // #1

    // S1: x1 = relu(x @ W1 + b1) -> X1 (B from L2)
    {
        float C[2][4];
        run_mma<10,2,true>(IN, INSTR, g_pk+PK_W1, C, warp_m, warp_n, g, t, lane);
        epi_store<2,true,true,true>(C, X1, 68, BIA, warp_m, warp_n, g, t);
    }
    __syncthreads();                                           // #2

    // S4: sel = x1 @ Wq_all -> fragment registers (pre-scaled by 1/sqrt(d))
    float sf[4][4];
    {
        float C[4][4];
        run_mma<8,4,true>(X1, 68, g_pk+PK_WQ, C, warp_m, warp_n, g, t, lane);
#pragma unroll
        for (int nt=0;nt<4;nt++)
#pragma unroll
            for (int j=0;j<4;j++) sf[nt][j] = C[nt][j]*LSCALE;
    }
    // S2: x2 = relu(x1 @ W2 + b2) -> ACT2
    {
        float C[2][4];
        run_mma<8,2,true>(X1, 68, g_pk+PK_W2, C, warp_m, warp_n, g, t, lane);
        epi_store<2,true,true,true>(C, ACT2, 132, BIA+64, warp_m, warp_n, g, t);
    }
    __syncthreads();                                           // #3

    // S3: x3_self = x2 @ w3_self -> registers
    float x3s[2][4];
    run_mma<8,2,true>(ACT2, 132, g_pk+PK_W3S, x3s, warp_m, warp_n, g, t, lane);
    // stage agent-0 inputs (IN free: S1 reads done at #2)
    stage_agent(IN, state_others, act_others, B, b0, 0, tid);
    cp_wait0();
    __syncthreads();                                           // #4

    // register softmax state + ov accumulators
    float m0 = -1e30f, m1 = -1e30f, s0 = 0.f, s1 = 0.f;
    float ov[4][4];
#pragma unroll
    for (int nt=0;nt<4;nt++)
#pragma unroll
        for (int j=0;j<4;j++) ov[nt][j]=0.f;

    // ---- agent loop: 2 syncs per iteration ----
    for (int a = 0; a < 7; a++){
        // enc = relu(inp @ We[a] + be[a]) -> ACT2 (bias read from global be)
        {
            float C[4][4];
            run_mma<11,4,false>(IN, INSTR, WSPK, C, warp_m, warp_n, g, t, lane);
            epi_store<4,true,true,true>(C, ACT2, 132, be + a*128, warp_m, warp_n, g, t);
        }
        __syncthreads();

        // prefetch next agent (overlaps keys/logits/vals below)
        if (a < 6){
            copy_pk(WSPK, g_pk+PK_WE + (a+1)*11264, 11264, tid);
            cp_commit();
            stage_agent(IN, state_others, act_others, B, b0, a+1, tid);
        }

        // keys MMA (B from L2) -> fragment logits -> register softmax
        float lg0, lg1;
        {
            float Ck[4][4];
            run_mma<16,4,true>(ACT2, 132, g_pk+PK_WK, Ck, warp_m, warp_n, g, t, lane);
            float p0 = 0.f, p1 = 0.f;
#pragma unroll
            for (int nt=0;nt<4;nt++){
                p0 += Ck[nt][0]*sf[nt][0] + Ck[nt][1]*sf[nt][1];
                p1 += Ck[nt][2]*sf[nt][2] + Ck[nt][3]*sf[nt][3];
            }
            p0 += __shfl_xor_sync(0xffffffffu, p0, 1);
            p0 += __shfl_xor_sync(0xffffffffu, p0, 2);
            p1 += __shfl_xor_sync(0xffffffffu, p1, 1);
            p1 += __shfl_xor_sync(0xffffffffu, p1, 2);
            lg0 = p0; lg1 = p1;
        }
        float mn0 = fmaxf(m0, lg0), mn1 = fmaxf(m1, lg1);
        float al0 = __expf(m0 - mn0), al1 = __expf(m1 - mn1);
        float pv0 = __expf(lg0 - mn0), pv1 = __expf(lg1 - mn1);
        s0 = s0*al0 + pv0; s1 = s1*al1 + pv1;
        m0 = mn0; m1 = mn1;

        // vals MMA (B = resident Wv) + local epilogue into ov
        {
            float Cv[4][4];
            run_mma<16,4,false>(ACT2, 132, WVPK, Cv, warp_m, warp_n, g, t, lane);
#pragma unroll
            for (int nt=0;nt<4;nt++){
                int col = warp_n*32 + nt*8 + 2*t;
                float bv0 = BIA[128+col], bv1 = BIA[128+col+1];
                float v0 = fmaxf(Cv[nt][0]+bv0, 0.f);
                float v1 = fmaxf(Cv[nt][1]+bv1, 0.f);
                float v2 = fmaxf(Cv[nt][2]+bv0, 0.f);
                float v3 = fmaxf(Cv[nt][3]+bv1, 0.f);
                ov[nt][0] = ov[nt][0]*al0 + pv0*v0;
                ov[nt][1] = ov[nt][1]*al0 + pv0*v1;
                ov[nt][2] = ov[nt][2]*al1 + pv1*v2;
                ov[nt][3] = ov[nt][3]*al1 + pv1*v3;
            }
        }
        cp_wait0();
        __syncthreads();
    }

    // x2_others = ov / s -> ACT2 (tf32), fragment-local
    {
        int r0 = warp_m*16 + g, r1 = r0 + 8;
        float i0 = 1.f / s0, i1 = 1.f / s1;
#pragma unroll
        for (int nt=0;nt<4;nt++){
            int col = warp_n*32 + nt*8 + 2*t;
            *reinterpret_cast<float2*>(ACT2 + r0*132 + col) =
                make_float2(tf32f(ov[nt][0]*i0), tf32f(ov[nt][1]*i0));
            *reinterpret_cast<float2*>(ACT2 + r1*132 + col) =
                make_float2(tf32f(ov[nt][2]*i1), tf32f(ov[nt][3]*i1));
        }
    }
    __syncthreads();

    // S8: x3o = x2o @ w3_others (B from L2); x3 = relu(x3_self + x3o); dot Wout
    {
        float C[2][4];
        run_mma<16,2,true>(ACT2, 132, g_pk+PK_W3O, C, warp_m, warp_n, g, t, lane);
        int r0 = warp_m*16 + g;
        float pr0 = 0.f, pr1 = 0.f;
#pragma unroll
        for (int nt=0;nt<2;nt++){
            int col = warp_n*16 + nt*8 + 2*t;
            float w0 = BIA[256+col], w1 = BIA[256+col+1];
            pr0 += fmaxf(C[nt][0]+x3s[nt][0], 0.f)*w0 + fmaxf(C[nt][1]+x3s[nt][1], 0.f)*w1;
            pr1 += fmaxf(C[nt][2]+x3s[nt][2], 0.f)*w0 + fmaxf(C[nt][3]+x3s[nt][3], 0.f)*w1;
        }
        pr0 += __shfl_xor_sync(0xffffffffu, pr0, 1);
        pr1 += __shfl_xor_sync(0xffffffffu, pr1, 1);
        pr0 += __shfl_xor_sync(0xffffffffu, pr0, 2);
        pr1 += __shfl_xor_sync(0xffffffffu, pr1, 2);
        if (t == 0){
            RED[warp_n*64 + r0]     = pr0;
            RED[warp_n*64 + r0 + 8] = pr1;
        }
    }
    __syncthreads();
    if (tid < 64){
        out[b0 + tid] = RED[tid] + RED[64+tid] + RED[128+tid] + RED[192+tid] + bout[0];
    }
}

extern "C" void kernel_launch(void* const* d_in, const int* in_sizes, int n_in,
                              void* d_out, int out_size)
{
    const float* state_one    = (const float*)d_in[0];
    const float* act_one      = (const float*)d_in[1];
    const float* state_others = (const float*)d_in[2];
    const float* act_others   = (const float*)d_in[3];
    const float* W1   = (const float*)d_in[4];
    const float* b1   = (const float*)d_in[5];
    const float* W2   = (const float*)d_in[6];
    const float* b2   = (const float*)d_in[7];
    const float* w3s  = (const float*)d_in[8];
    const float* We   = (const float*)d_in[9];
    const float* be   = (const float*)d_in[10];
    const float* Wk   = (const float*)d_in[11];
    const float* Wq   = (const float*)d_in[12];
    const float* Wv   = (const float*)d_in[13];
    const float* bv   = (const float*)d_in[14];
    const float* w3o  = (const float*)d_in[15];
    const float* Wout = (const float*)d_in[16];
    const float* bout = (const float*)d_in[17];
    float* out = (float*)d_out;

    int B = in_sizes[0] / 64;

    prep_kernel<<<138, 256>>>(W1, Wq, W2, w3s, w3o, Wk, Wv, We);

    int smem_bytes = SMEM_FLOATS * sizeof(float);
    cudaFuncSetAttribute(ac_kernel, cudaFuncAttributeMaxDynamicSharedMemorySize, smem_bytes);
    ac_kernel<<<B/BT, NTHREADS, smem_bytes>>>(
        state_one, act_one, state_others, act_others,
        b1, b2, be, bv, Wout, bout, out, B);
}

// round 10
// speedup vs baseline: 3.9143x; 1.1437x over previous
#include <cuda_runtime.h>
#include <cstdint>

#define NTHREADS 256
#define BT 32
#define LSCALE 0.17677669529663687f  // 1/sqrt(32)
#define INSTR 92

// ---------------- packed-weight device buffer (floats) ----------------
#define PK_W1   0        // KS=10 NTW=2 -> 5120
#define PK_WQ   5120     // KS=8  NTW=4 -> 8192
#define PK_W2   13312    // KS=8  NTW=2 -> 4096
#define PK_W3S  17408    // KS=8  NTW=2 -> 4096
#define PK_W3O  21504    // KS=16 NTW=2 -> 8192
#define PK_WK   29696    // KS=16 NTW=4 -> 16384
#define PK_WV   46080    // KS=16 NTW=4 -> 16384
#define PK_WE   62464    // 7 * 11264 = 78848
#define PK_TOTAL 141312
__device__ float g_pk[PK_TOTAL];

// ---------------- smem layout (floats) ----------------
#define OFF_WVPK 0        // Wv packed resident (16384)
#define OFF_IN   16384    // [32][92] inputs (2944)
#define OFF_ACT2 19328    // [32][132] sel-temp/x2/enc/x2_others (4224)
#define OFF_X1   23552    // [32][68] x1 (2176)
#define OFF_BIA  25728    // b1(64) b2(64) bv(128) Wout(64) = 320
#define OFF_RED  26048    // 128
#define SMEM_FLOATS 26176 // 104704 bytes -> 2 CTAs/SM

__device__ __forceinline__ float tf32f(float x){
    uint32_t u; asm("cvt.rna.tf32.f32 %0, %1;" : "=r"(u) : "f"(x));
    return __uint_as_float(u);
}

// ================= prep kernel: pack weights fragment-major =================
#define PACK_REGION(DST, KS, NTW, KACT, SRCEXPR) do {                      \
    int SZ_ = (KS)*4*2*32*(NTW);                                           \
    for (int i_ = t0; i_ < SZ_; i_ += NT){                                 \
        int tile = i_ % (NTW); int r_ = i_ / (NTW);                        \
        int lane_ = r_ & 31; r_ >>= 5;                                     \
        int half_ = r_ & 1;  r_ >>= 1;                                     \
        int nw_ = r_ & 3;    int ks_ = r_ >> 2;                            \
        int k = ks_*8 + (lane_ & 3) + half_*4;                             \
        int n = nw_*8*(NTW) + tile*8 + (lane_ >> 2);                       \
        float v_ = 0.f;                                                    \
        if (k < (KACT)) { v_ = (SRCEXPR); }                                \
        (DST)[i_] = tf32f(v_);                                             \
    } } while(0)

__global__ void prep_kernel(const float* __restrict__ W1, const float* __restrict__ Wq,
                            const float* __restrict__ W2, const float* __restrict__ w3s,
                            const float* __restrict__ w3o, const float* __restrict__ Wk,
                            const float* __restrict__ Wv, const float* __restrict__ We){
    int t0 = blockIdx.x*blockDim.x + threadIdx.x;
    int NT = gridDim.x*blockDim.x;
    PACK_REGION(g_pk+PK_W1, 10, 2, 78, W1[k*64+n]);
    PACK_REGION(g_pk+PK_WQ,  8, 4, 64, Wq[(n>>5)*2048 + k*32 + (n&31)]);
    PACK_REGION(g_pk+PK_W2,  8, 2, 64, W2[k*64+n]);
    PACK_REGION(g_pk+PK_W3S, 8, 2, 64, w3s[k*64+n]);
    PACK_REGION(g_pk+PK_W3O,16, 2,128, w3o[k*64+n]);
    PACK_REGION(g_pk+PK_WK, 16, 4,128, Wk[(n>>5)*4096 + k*32 + (n&31)]);
    PACK_REGION(g_pk+PK_WV, 16, 4,128, Wv[(n>>5)*4096 + k*32 + (n&31)]);
    for (int a = 0; a < 7; a++){
        PACK_REGION(g_pk+PK_WE + a*11264, 11, 4, 82, We[a*82*128 + k*128 + n]);
    }
}

// ================= main kernel helpers =================
__device__ __forceinline__ void cp_async16(float* dst, const float* src){
    uint32_t s = (uint32_t)__cvta_generic_to_shared(dst);
    asm volatile("cp.async.cg.shared.global [%0], [%1], 16;" :: "r"(s), "l"(src));
}
__device__ __forceinline__ void cp_commit(){
    asm volatile("cp.async.commit_group;");
}
__device__ __forceinline__ void cp_wait0(){
    asm volatile("cp.async.wait_group 0;" ::: "memory");
}

__device__ __forceinline__ void mma8(float* c, const uint32_t* a, uint32_t b0, uint32_t b1){
    asm volatile("mma.sync.aligned.m16n8k8.row.col.f32.tf32.tf32.f32 "
        "{%0,%1,%2,%3},{%4,%5,%6,%7},{%8,%9},{%0,%1,%2,%3};"
        : "+f"(c[0]),"+f"(c[1]),"+f"(c[2]),"+f"(c[3])
        : "r"(a[0]),"r"(a[1]),"r"(a[2]),"r"(a[3]),"r"(b0),"r"(b1));
}

// warp tile: 16 rows (warp_m 0..1) x 8*NTW cols (warp_n 0..3); BG=1 -> B from L2
template<int KS, int NTW, bool BG>
__device__ __forceinline__ void run_mma(const float* __restrict__ A, int astr,
                                        const float* __restrict__ Bpk,
                                        float (&C)[NTW][4],
                                        int warp_m, int warp_n, int g, int t, int lane)
{
#pragma unroll
    for (int nt=0;nt<NTW;nt++)
#pragma unroll
        for (int j=0;j<4;j++) C[nt][j]=0.f;
    const float* ap = A + (warp_m*16 + g)*astr + t;
#pragma unroll
    for (int ks=0; ks<KS; ks++){
        uint32_t a[4];
        a[0] = __float_as_uint(ap[ks*8]);
        a[1] = __float_as_uint(ap[8*astr + ks*8]);
        a[2] = __float_as_uint(ap[ks*8 + 4]);
        a[3] = __float_as_uint(ap[8*astr + ks*8 + 4]);
        const float* bp = Bpk + ((size_t)((ks*4 + warp_n)*2)*32 + lane)*NTW;
        uint32_t b0[NTW], b1[NTW];
        if constexpr (NTW==4){
            float4 x, y;
            if constexpr (BG){
                x = __ldg(reinterpret_cast<const float4*>(bp));
                y = __ldg(reinterpret_cast<const float4*>(bp + 32*4));
            } else {
                x = *reinterpret_cast<const float4*>(bp);
                y = *reinterpret_cast<const float4*>(bp + 32*4);
            }
            b0[0]=__float_as_uint(x.x); b0[1]=__float_as_uint(x.y);
            b0[2]=__float_as_uint(x.z); b0[3]=__float_as_uint(x.w);
            b1[0]=__float_as_uint(y.x); b1[1]=__float_as_uint(y.y);
            b1[2]=__float_as_uint(y.z); b1[3]=__float_as_uint(y.w);
        } else {
            float2 x, y;
            if constexpr (BG){
                x = __ldg(reinterpret_cast<const float2*>(bp));
                y = __ldg(reinterpret_cast<const float2*>(bp + 32*2));
            } else {
                x = *reinterpret_cast<const float2*>(bp);
                y = *reinterpret_cast<const float2*>(bp + 32*2);
            }
            b0[0]=__float_as_uint(x.x); b0[1]=__float_as_uint(x.y);
            b1[0]=__float_as_uint(y.x); b1[1]=__float_as_uint(y.y);
        }
#pragma unroll
        for (int nt=0;nt<NTW;nt++)
            mma8(C[nt], a, b0[nt], b1[nt]);
    }
}

template<int NTW, bool RELU, bool BIAS, bool CVT>
__device__ __forceinline__ void epi_store(float (&C)[NTW][4], float* __restrict__ O, int ostr,
                                          const float* __restrict__ bias,
                                          int warp_m, int warp_n, int g, int t)
{
    int r0 = warp_m*16 + g;
#pragma unroll
    for (int nt=0;nt<NTW;nt++){
        int col = warp_n*(8*NTW) + nt*8 + 2*t;
        float bb0 = BIAS ? bias[col]   : 0.f;
        float bb1 = BIAS ? bias[col+1] : 0.f;
        float v0 = C[nt][0]+bb0, v1 = C[nt][1]+bb1;
        float v2 = C[nt][2]+bb0, v3 = C[nt][3]+bb1;
        if (RELU){ v0=fmaxf(v0,0.f); v1=fmaxf(v1,0.f); v2=fmaxf(v2,0.f); v3=fmaxf(v3,0.f); }
        if (CVT){ v0=tf32f(v0); v1=tf32f(v1); v2=tf32f(v2); v3=tf32f(v3); }
        *reinterpret_cast<float2*>(O + r0*ostr + col)     = make_float2(v0,v1);
        *reinterpret_cast<float2*>(O + (r0+8)*ostr + col) = make_float2(v2,v3);
    }
}

__device__ __forceinline__ void stage_agent(float* IN, const float* __restrict__ so,
                                            const float* __restrict__ ao,
                                            int B, int b0, int a, int tid){
    for (int i = tid; i < BT*22; i += NTHREADS){
        int row = i/22, c4 = i - row*22; int c = c4*4;
        float4 v;
        if (c4 < 16){
            v = *reinterpret_cast<const float4*>(so + ((size_t)a*B + b0+row)*64 + c);
        } else {
            const float* ap = ao + ((size_t)a*B + b0+row)*18;
            int j = c - 64;
            v.x = (j   < 18) ? ap[j]   : 0.f;
            v.y = (j+1 < 18) ? ap[j+1] : 0.f;
            v.z = (j+2 < 18) ? ap[j+2] : 0.f;
            v.w = (j+3 < 18) ? ap[j+3] : 0.f;
        }
        v.x=tf32f(v.x); v.y=tf32f(v.y); v.z=tf32f(v.z); v.w=tf32f(v.w);
        *reinterpret_cast<float4*>(IN + row*INSTR + c) = v;
    }
}

__global__ void __launch_bounds__(NTHREADS,2) ac_kernel(
    const float* __restrict__ state_one, const float* __restrict__ act_one,
    const float* __restrict__ state_others, const float* __restrict__ act_others,
    const float* __restrict__ b1, const float* __restrict__ b2,
    const float* __restrict__ be, const float* __restrict__ bv,
    const float* __restrict__ Wout, const float* __restrict__ bout,
    float* __restrict__ out, int B)
{
    extern __shared__ float sm[];
    float* WVPK = sm + OFF_WVPK;
    float* IN   = sm + OFF_IN;
    float* ACT2 = sm + OFF_ACT2;
    float* X1   = sm + OFF_X1;
    float* BIA  = sm + OFF_BIA;
    float* RED  = sm + OFF_RED;

    const int tid = threadIdx.x;
    const int lane = tid & 31;
    const int warp = tid >> 5;
    const int g = lane >> 2, t = lane & 3;
    const int warp_m = warp & 1, warp_n = warp >> 1;
    const int b0 = blockIdx.x * BT;

    // ---- initial staging: Wv via cp.async; self inputs + biases via STS ----
    for (int i = tid*4; i < 16384; i += NTHREADS*4) cp_async16(WVPK+i, g_pk+PK_WV+i);
    cp_commit();
    for (int i = tid; i < BT*20; i += NTHREADS){
        int row = i/20, c4 = i - row*20; int c = c4*4;
        float4 v;
        if (c4 < 16){
            v = *reinterpret_cast<const float4*>(state_one + (size_t)(b0+row)*64 + c);
        } else {
            const float* ap = act_one + (size_t)(b0+row)*14;
            int j = c - 64;
            v.x = (j   < 14) ? ap[j]   : 0.f;
            v.y = (j+1 < 14) ? ap[j+1] : 0.f;
            v.z = (j+2 < 14) ? ap[j+2] : 0.f;
            v.w = (j+3 < 14) ? ap[j+3] : 0.f;
        }
        v.x=tf32f(v.x); v.y=tf32f(v.y); v.z=tf32f(v.z); v.w=tf32f(v.w);
        *reinterpret_cast<float4*>(IN + row*INSTR + c) = v;
    }
    for (int i = tid; i < 320; i += NTHREADS){
        float v;
        if (i < 64) v = b1[i];
        else if (i < 128) v = b2[i-64];
        else if (i < 256) v = bv[i-128];
        else v = Wout[i-256];
        BIA[i] = v;
    }
    __syncthreads();                                           // #1

    // S1: x1 = relu(x @ W1 + b1) -> X1 (B from L2)
    {
        float C[2][4];
        run_mma<10,2,true>(IN, INSTR, g_pk+PK_W1, C, warp_m, warp_n, g, t, lane);
        epi_store<2,true,true,true>(C, X1, 68, BIA, warp_m, warp_n, g, t);
    }
    __syncthreads();                                           // #2

    // S4: sel = x1 @ Wq_all -> fragment registers (pre-scaled by 1/sqrt(d))
    float sf[4][4];
    {
        float C[4][4];
        run_mma<8,4,true>(X1, 68, g_pk+PK_WQ, C, warp_m, warp_n, g, t, lane);
#pragma unroll
        for (int nt=0;nt<4;nt++)
#pragma unroll
            for (int j=0;j<4;j++) sf[nt][j] = C[nt][j]*LSCALE;
    }
    // S2: x2 = relu(x1 @ W2 + b2) -> ACT2
    {
        float C[2][4];
        run_mma<8,2,true>(X1, 68, g_pk+PK_W2, C, warp_m, warp_n, g, t, lane);
        epi_store<2,true,true,true>(C, ACT2, 132, BIA+64, warp_m, warp_n, g, t);
    }
    __syncthreads();                                           // #3

    // S3: x3_self = x2 @ w3_self -> registers
    float x3s[2][4];
    run_mma<8,2,true>(ACT2, 132, g_pk+PK_W3S, x3s, warp_m, warp_n, g, t, lane);
    // stage agent-0 inputs (IN free after #2)
    stage_agent(IN, state_others, act_others, B, b0, 0, tid);
    cp_wait0();
    __syncthreads();                                           // #4

    // register softmax state + ov accumulators
    float m0 = -1e30f, m1 = -1e30f, s0 = 0.f, s1 = 0.f;
    float ov[4][4];
#pragma unroll
    for (int nt=0;nt<4;nt++)
#pragma unroll
        for (int j=0;j<4;j++) ov[nt][j]=0.f;

    // ---- agent loop: 2 syncs per iteration, no in-loop cp.async ----
    for (int a = 0; a < 7; a++){
        // enc = relu(inp @ We[a] + be[a]) -> ACT2 (We B-frags from L2)
        {
            float C[4][4];
            run_mma<11,4,true>(IN, INSTR, g_pk+PK_WE + a*11264, C, warp_m, warp_n, g, t, lane);
            epi_store<4,true,true,true>(C, ACT2, 132, be + a*128, warp_m, warp_n, g, t);
        }
        __syncthreads();

        // stage next agent inputs (overlaps keys/logits/vals below)
        if (a < 6) stage_agent(IN, state_others, act_others, B, b0, a+1, tid);

        // keys MMA (Wk from L2) -> fragment logits -> register softmax
        float lg0, lg1;
        {
            float Ck[4][4];
            run_mma<16,4,true>(ACT2, 132, g_pk+PK_WK, Ck, warp_m, warp_n, g, t, lane);
            float p0 = 0.f, p1 = 0.f;
#pragma unroll
            for (int nt=0;nt<4;nt++){
                p0 += Ck[nt][0]*sf[nt][0] + Ck[nt][1]*sf[nt][1];
                p1 += Ck[nt][2]*sf[nt][2] + Ck[nt][3]*sf[nt][3];
            }
            p0 += __shfl_xor_sync(0xffffffffu, p0, 1);
            p0 += __shfl_xor_sync(0xffffffffu, p0, 2);
            p1 += __shfl_xor_sync(0xffffffffu, p1, 1);
            p1 += __shfl_xor_sync(0xffffffffu, p1, 2);
            lg0 = p0; lg1 = p1;
        }
        float mn0 = fmaxf(m0, lg0), mn1 = fmaxf(m1, lg1);
        float al0 = __expf(m0 - mn0), al1 = __expf(m1 - mn1);
        float pv0 = __expf(lg0 - mn0), pv1 = __expf(lg1 - mn1);
        s0 = s0*al0 + pv0; s1 = s1*al1 + pv1;
        m0 = mn0; m1 = mn1;

        // vals MMA (B = resident Wv in smem) + local epilogue into ov
        {
            float Cv[4][4];
            run_mma<16,4,false>(ACT2, 132, WVPK, Cv, warp_m, warp_n, g, t, lane);
#pragma unroll
            for (int nt=0;nt<4;nt++){
                int col = warp_n*32 + nt*8 + 2*t;
                float bv0 = BIA[128+col], bv1 = BIA[128+col+1];
                float v0 = fmaxf(Cv[nt][0]+bv0, 0.f);
                float v1 = fmaxf(Cv[nt][1]+bv1, 0.f);
                float v2 = fmaxf(Cv[nt][2]+bv0, 0.f);
                float v3 = fmaxf(Cv[nt][3]+bv1, 0.f);
                ov[nt][0] = ov[nt][0]*al0 + pv0*v0;
                ov[nt][1] = ov[nt][1]*al0 + pv0*v1;
                ov[nt][2] = ov[nt][2]*al1 + pv1*v2;
                ov[nt][3] = ov[nt][3]*al1 + pv1*v3;
            }
        }
        __syncthreads();
    }

    // x2_others = ov / s -> ACT2 (tf32), fragment-local
    {
        int r0 = warp_m*16 + g, r1 = r0 + 8;
        float i0 = 1.f / s0, i1 = 1.f / s1;
#pragma unroll
        for (int nt=0;nt<4;nt++){
            int col = warp_n*32 + nt*8 + 2*t;
            *reinterpret_cast<float2*>(ACT2 + r0*132 + col) =
                make_float2(tf32f(ov[nt][0]*i0), tf32f(ov[nt][1]*i0));
            *reinterpret_cast<float2*>(ACT2 + r1*132 + col) =
                make_float2(tf32f(ov[nt][2]*i1), tf32f(ov[nt][3]*i1));
        }
    }
    __syncthreads();

    // S8: x3o = x2o @ w3_others (B from L2); x3 = relu(x3_self + x3o); dot Wout
    {
        float C[2][4];
        run_mma<16,2,true>(ACT2, 132, g_pk+PK_W3O, C, warp_m, warp_n, g, t, lane);
        int r0 = warp_m*16 + g;
        float pr0 = 0.f, pr1 = 0.f;
#pragma unroll
        for (int nt=0;nt<2;nt++){
            int col = warp_n*16 + nt*8 + 2*t;
            float w0 = BIA[256+col], w1 = BIA[256+col+1];
            pr0 += fmaxf(C[nt][0]+x3s[nt][0], 0.f)*w0 + fmaxf(C[nt][1]+x3s[nt][1], 0.f)*w1;
            pr1 += fmaxf(C[nt][2]+x3s[nt][2], 0.f)*w0 + fmaxf(C[nt][3]+x3s[nt][3], 0.f)*w1;
        }
        pr0 += __shfl_xor_sync(0xffffffffu, pr0, 1);
        pr1 += __shfl_xor_sync(0xffffffffu, pr1, 1);
        pr0 += __shfl_xor_sync(0xffffffffu, pr0, 2);
        pr1 += __shfl_xor_sync(0xffffffffu, pr1, 2);
        if (t == 0){
            RED[warp_n*32 + r0]     = pr0;
            RED[warp_n*32 + r0 + 8] = pr1;
        }
    }
    __syncthreads();
    if (tid < 32){
        out[b0 + tid] = RED[tid] + RED[32+tid] + RED[64+tid] + RED[96+tid] + bout[0];
    }
}

extern "C" void kernel_launch(void* const* d_in, const int* in_sizes, int n_in,
                              void* d_out, int out_size)
{
    const float* state_one    = (const float*)d_in[0];
    const float* act_one      = (const float*)d_in[1];
    const float* state_others = (const float*)d_in[2];
    const float* act_others   = (const float*)d_in[3];
    const float* W1   = (const float*)d_in[4];
    const float* b1   = (const float*)d_in[5];
    const float* W2   = (const float*)d_in[6];
    const float* b2   = (const float*)d_in[7];
    const float* w3s  = (const float*)d_in[8];
    const float* We   = (const float*)d_in[9];
    const float* be   = (const float*)d_in[10];
    const float* Wk   = (const float*)d_in[11];
    const float* Wq   = (const float*)d_in[12];
    const float* Wv   = (const float*)d_in[13];
    const float* bv   = (const float*)d_in[14];
    const float* w3o  = (const float*)d_in[15];
    const float* Wout = (const float*)d_in[16];
    const float* bout = (const float*)d_in[17];
    float* out = (float*)d_out;

    int B = in_sizes[0] / 64;

    prep_kernel<<<138, 256>>>(W1, Wq, W2, w3s, w3o, Wk, Wv, We);

    int smem_bytes = SMEM_FLOATS * sizeof(float);
    cudaFuncSetAttribute(ac_kernel, cudaFuncAttributeMaxDynamicSharedMemorySize, smem_bytes);
    ac_kernel<<<B/BT, NTHREADS, smem_bytes>>>(
        state_one, act_one, state_others, act_others,
        b1, b2, be, bv, Wout, bout, out, B);
}